// round 13
// baseline (speedup 1.0000x reference)
#include <cuda_runtime.h>
#include <cuda_fp16.h>
#include <cstdint>

// MeanShift: B=2, C=3, N=9216, 5 iters.
// w_ij = exp2( (2g*y_i).x_j - g||x_j||^2 - g||y_i||^2 ), g = 50/ln2.
// HMMA accumulation (mma.sync m16n8k16 f16xf16+f32), precomputed fp16
// B-fragment table. R13 = R12 + explicit next-window software pipeline:
// at regs=72/128 there is headroom for a full prefetch set, so window w+1's
// 4 LDS.128 + 2 LDS.32 issue under window w's cvt/ex2/MMA tail.
// 512 thr = 4 query-pairs x 4 j-splits, 32 q/warp, barrier-free mainloop.

#define NPTS 9216
#define NB 2
#define GG 72.13475204444817f
#define TPB 512
#define NJS 4
#define WINS_PER_JS 144          // 576 windows of 16 points, split 4 ways
#define NWINT 576

typedef unsigned long long u64;
typedef unsigned int u32;

__device__ float4 g_pts[NB * NPTS];   // [2*jp]={x0,x1,y0,y1}, [2*jp+1]={z0,z1,b0,b1}
__device__ float4 g_y[2][NB * NPTS];
__device__ __align__(16) unsigned char g_feat[NB * NWINT * 128];  // fp16 B-frag table

// smem: points [0,147456) | feat [147456,221184) | psum [221184,229376)
#define SO_FEAT 147456
#define SO_PSUM 221184
#define SMEMSZ  229376

static __device__ __forceinline__ u64 pk2(float a, float b) {
    u64 r; asm("mov.b64 %0,{%1,%2};" : "=l"(r) : "f"(a), "f"(b)); return r;
}
static __device__ __forceinline__ u64 fma2(u64 a, u64 b, u64 c) {
    u64 d; asm("fma.rn.f32x2 %0,%1,%2,%3;" : "=l"(d) : "l"(a), "l"(b), "l"(c)); return d;
}
static __device__ __forceinline__ u64 add2(u64 a, u64 b) {
    u64 d; asm("add.rn.f32x2 %0,%1,%2;" : "=l"(d) : "l"(a), "l"(b)); return d;
}
static __device__ __forceinline__ void lds2(u32 a, u64& x, u64& y) {
    asm volatile("ld.shared.v2.u64 {%0,%1},[%2];" : "=l"(x), "=l"(y) : "r"(a));
}
static __device__ __forceinline__ u32 lds32(u32 a) {
    u32 v; asm volatile("ld.shared.b32 %0,[%1];" : "=r"(v) : "r"(a)); return v;
}
// f32x2 arg -> fp16x2 weight pair (lo stays lo): cvt + one ex2.approx.f16x2.
static __device__ __forceinline__ u32 wgt2(u64 t) {
    u32 h;
    asm("{\n\t.reg .f32 lo,hi;\n\tmov.b64 {lo,hi},%1;\n\t"
        "cvt.rn.f16x2.f32 %0,hi,lo;\n\tex2.approx.f16x2 %0,%0;\n\t}" : "=r"(h) : "l"(t));
    return h;
}
static __device__ __forceinline__ void mma16816(
    float& c0, float& c1, float& c2, float& c3,
    u32 a0, u32 a1, u32 a2, u32 a3, u32 b0, u32 b1) {
    asm volatile("mma.sync.aligned.m16n8k16.row.col.f32.f16.f16.f32 "
        "{%0,%1,%2,%3}, {%4,%5,%6,%7}, {%8,%9}, {%0,%1,%2,%3};"
        : "+f"(c0), "+f"(c1), "+f"(c2), "+f"(c3)
        : "r"(a0), "r"(a1), "r"(a2), "r"(a3), "r"(b0), "r"(b1));
}

__global__ void prep_kernel(const float* __restrict__ x) {
    int idx = blockIdx.x * blockDim.x + threadIdx.x;
    if (idx >= NB * NPTS) return;
    int b = idx / NPTS, n = idx - b * NPTS;
    float px = x[(b * 3 + 0) * NPTS + n];
    float py = x[(b * 3 + 1) * NPTS + n];
    float pz = x[(b * 3 + 2) * NPTS + n];
    float bn = -GG * (px * px + py * py + pz * pz);
    int jp = n >> 1, l = n & 1;
    float* base = (float*)&g_pts[b * NPTS + 2 * jp];
    base[0 + l] = px; base[2 + l] = py; base[4 + l] = pz; base[6 + l] = bn;
    g_y[0][b * NPTS + n] = make_float4(px, py, pz, 0.f);

    // fp16 B-fragment table: window = n>>4; row g: 0:x 1:y 2:z 3:1.0
    int i = n & 15;
    unsigned char* fb = g_feat + ((size_t)(b * NWINT + (n >> 4))) * 128
                      + (i >> 1) * 4 + (i & 1) * 2;
    *(__half*)(fb + 0)  = __float2half(px);
    *(__half*)(fb + 32) = __float2half(py);
    *(__half*)(fb + 64) = __float2half(pz);
    *(__half*)(fb + 96) = __float2half(1.0f);
}

__global__ __launch_bounds__(TPB, 1) void iter_kernel(int src, int dst, float* __restrict__ out) {
    extern __shared__ __align__(16) unsigned char smem[];
    const int tid = threadIdx.x, wid = tid >> 5, lane = tid & 31;
    const int g = lane >> 2, t = lane & 3;
    const int b = blockIdx.y, tile = blockIdx.x;
    u32 sb = (u32)__cvta_generic_to_shared(smem);

    {   // stage points (147456 B) + feature table (73728 B)
        const float4* gp = g_pts + b * NPTS;
        float4* sp = (float4*)smem;
        for (int i = tid; i < NPTS; i += TPB) sp[i] = gp[i];
        const float4* gf = (const float4*)(g_feat + (size_t)b * NWINT * 128);
        float4* sf = (float4*)(smem + SO_FEAT);
        for (int i = tid; i < NWINT * 8; i += TPB) sf[i] = gf[i];
    }
    __syncthreads();

    const int qp = wid & 3;            // query-pair: 32 queries
    const int js = wid >> 2;           // j-split 0..3
    const int qA0 = qp * 32 + g;
    const int qA1 = qA0 + 8;
    const int qB0 = qA0 + 16;
    const int qB1 = qA0 + 24;

    const float tg = 2.0f * GG;
    u64 axA0, ayA0, azA0, ppA0, axA1, ayA1, azA1, ppA1;
    u64 axB0, ayB0, azB0, ppB0, axB1, ayB1, azB1, ppB1;
    {
        float4 y;
        y = g_y[src][b * NPTS + tile * 128 + qA0];
        axA0 = pk2(tg * y.x, tg * y.x); ayA0 = pk2(tg * y.y, tg * y.y);
        azA0 = pk2(tg * y.z, tg * y.z);
        float p = -GG * (y.x * y.x + y.y * y.y + y.z * y.z); ppA0 = pk2(p, p);
        y = g_y[src][b * NPTS + tile * 128 + qA1];
        axA1 = pk2(tg * y.x, tg * y.x); ayA1 = pk2(tg * y.y, tg * y.y);
        azA1 = pk2(tg * y.z, tg * y.z);
        p = -GG * (y.x * y.x + y.y * y.y + y.z * y.z); ppA1 = pk2(p, p);
        y = g_y[src][b * NPTS + tile * 128 + qB0];
        axB0 = pk2(tg * y.x, tg * y.x); ayB0 = pk2(tg * y.y, tg * y.y);
        azB0 = pk2(tg * y.z, tg * y.z);
        p = -GG * (y.x * y.x + y.y * y.y + y.z * y.z); ppB0 = pk2(p, p);
        y = g_y[src][b * NPTS + tile * 128 + qB1];
        axB1 = pk2(tg * y.x, tg * y.x); ayB1 = pk2(tg * y.y, tg * y.y);
        azB1 = pk2(tg * y.z, tg * y.z);
        p = -GG * (y.x * y.x + y.y * y.y + y.z * y.z); ppB1 = pk2(p, p);
    }

    const bool ldb = (g < 4);
    const int gm = (g < 4) ? g : 3;     // clamp -> in-bounds broadcast for g>=4

    float cA0 = 0.f, cA1 = 0.f, cA2 = 0.f, cA3 = 0.f;
    float cB0 = 0.f, cB1 = 0.f, cB2 = 0.f, cB3 = 0.f;

    u32 base = sb + (u32)(js * WINS_PER_JS) * 256u + 32u * (u32)t;
    u32 fb = sb + SO_FEAT + (u32)(js * WINS_PER_JS) * 128u + (u32)(gm * 32 + t * 4);

    // Software-pipelined: window w computes while w+1 loads.
    u64 xx0, yy0, zz0, bb0, xx1, yy1, zz1, bb1;
    u32 f0, f1;
    lds2(base, xx0, yy0);
    lds2(base + 16u, zz0, bb0);
    lds2(base + 128u, xx1, yy1);
    lds2(base + 144u, zz1, bb1);
    f0 = lds32(fb);
    f1 = lds32(fb + 16u);

    #pragma unroll 2
    for (int w = 0; w < WINS_PER_JS; w++) {
        // 8 args from current window regs.
        u64 tA00 = fma2(axA0, xx0, fma2(ayA0, yy0, fma2(azA0, zz0, add2(bb0, ppA0))));
        u64 tA10 = fma2(axA1, xx0, fma2(ayA1, yy0, fma2(azA1, zz0, add2(bb0, ppA1))));
        u64 tB00 = fma2(axB0, xx0, fma2(ayB0, yy0, fma2(azB0, zz0, add2(bb0, ppB0))));
        u64 tB10 = fma2(axB1, xx0, fma2(ayB1, yy0, fma2(azB1, zz0, add2(bb0, ppB1))));
        u64 tA01 = fma2(axA0, xx1, fma2(ayA0, yy1, fma2(azA0, zz1, add2(bb1, ppA0))));
        u64 tA11 = fma2(axA1, xx1, fma2(ayA1, yy1, fma2(azA1, zz1, add2(bb1, ppA1))));
        u64 tB01 = fma2(axB0, xx1, fma2(ayB0, yy1, fma2(azB0, zz1, add2(bb1, ppB0))));
        u64 tB11 = fma2(axB1, xx1, fma2(ayB1, yy1, fma2(azB1, zz1, add2(bb1, ppB1))));

        u32 b0 = ldb ? f0 : 0u;
        u32 b1 = ldb ? f1 : 0u;

        // Prefetch next window under the cvt/ex2/MMA tail.
        if (w + 1 < WINS_PER_JS) {
            base += 256u; fb += 128u;
            lds2(base, xx0, yy0);
            lds2(base + 16u, zz0, bb0);
            lds2(base + 128u, xx1, yy1);
            lds2(base + 144u, zz1, bb1);
            f0 = lds32(fb);
            f1 = lds32(fb + 16u);
        }

        mma16816(cA0, cA1, cA2, cA3,
                 wgt2(tA00), wgt2(tA10), wgt2(tA01), wgt2(tA11), b0, b1);
        mma16816(cB0, cB1, cB2, cB3,
                 wgt2(tB00), wgt2(tB10), wgt2(tB01), wgt2(tB11), b0, b1);
    }

    // D rows: cX0,cX1 = row q?0 cols {2t,2t+1}; cX2,cX3 = row q?1.
    float* ps = (float*)(smem + SO_PSUM);
    if (t == 0) {
        ps[(js * 128 + qA0) * 4 + 0] = cA0; ps[(js * 128 + qA0) * 4 + 1] = cA1;
        ps[(js * 128 + qA1) * 4 + 0] = cA2; ps[(js * 128 + qA1) * 4 + 1] = cA3;
        ps[(js * 128 + qB0) * 4 + 0] = cB0; ps[(js * 128 + qB0) * 4 + 1] = cB1;
        ps[(js * 128 + qB1) * 4 + 0] = cB2; ps[(js * 128 + qB1) * 4 + 1] = cB3;
    } else if (t == 1) {
        ps[(js * 128 + qA0) * 4 + 2] = cA0; ps[(js * 128 + qA0) * 4 + 3] = cA1;
        ps[(js * 128 + qA1) * 4 + 2] = cA2; ps[(js * 128 + qA1) * 4 + 3] = cA3;
        ps[(js * 128 + qB0) * 4 + 2] = cB0; ps[(js * 128 + qB0) * 4 + 3] = cB1;
        ps[(js * 128 + qB1) * 4 + 2] = cB2; ps[(js * 128 + qB1) * 4 + 3] = cB3;
    }
    __syncthreads();

    if (tid < 128) {
        float4* pv = (float4*)(smem + SO_PSUM);
        float4 a = pv[tid];
        #pragma unroll
        for (int k = 1; k < NJS; k++) {
            float4 s = pv[k * 128 + tid];
            a.x += s.x; a.y += s.y; a.z += s.z; a.w += s.w;
        }
        float inv = __fdividef(1.0f, a.w);
        float nx = a.x * inv, ny = a.y * inv, nz = a.z * inv;
        int qi = tile * 128 + tid;
        g_y[dst][b * NPTS + qi] = make_float4(nx, ny, nz, 0.f);
        if (out) {
            out[(b * 3 + 0) * NPTS + qi] = nx;
            out[(b * 3 + 1) * NPTS + qi] = ny;
            out[(b * 3 + 2) * NPTS + qi] = nz;
        }
    }
}

extern "C" void kernel_launch(void* const* d_in, const int* in_sizes, int n_in,
                              void* d_out, int out_size) {
    const float* x = (const float*)d_in[0];
    float* out = (float*)d_out;

    cudaFuncSetAttribute(iter_kernel, cudaFuncAttributeMaxDynamicSharedMemorySize, SMEMSZ);

    prep_kernel<<<(NB * NPTS + 255) / 256, 256>>>(x);

    dim3 grid(72, NB);
    for (int it = 0; it < 5; it++) {
        iter_kernel<<<grid, TPB, SMEMSZ>>>(it & 1, (it & 1) ^ 1, (it == 4) ? out : nullptr);
    }
}

// round 14
// speedup vs baseline: 1.0714x; 1.0714x over previous
#include <cuda_runtime.h>
#include <cuda_fp16.h>
#include <cstdint>

// MeanShift: B=2, C=3, N=9216, 5 iters.
// w_ij = exp2( (2g*y_i).x_j - g||x_j||^2 - g||y_i||^2 ), g = 50/ln2.
// HMMA accumulation (mma.sync m16n8k16 f16xf16+f32), precomputed fp16
// B-fragment table. R14 = R12 economics at 6 warps/SMSP: 768 thr =
// 4 query-pairs x 6 j-splits (96 windows each). psum is overlaid on the
// points region (dead after mainloop; extra __syncthreads() guards it),
// keeping SMEM at 221184 B. Barrier-free mainloop.

#define NPTS 9216
#define NB 2
#define GG 72.13475204444817f
#define TPB 768
#define NJS 6
#define WINS_PER_JS 96           // 576 windows of 16 points, split 6 ways
#define NWINT 576

typedef unsigned long long u64;
typedef unsigned int u32;

__device__ float4 g_pts[NB * NPTS];   // [2*jp]={x0,x1,y0,y1}, [2*jp+1]={z0,z1,b0,b1}
__device__ float4 g_y[2][NB * NPTS];
__device__ __align__(16) unsigned char g_feat[NB * NWINT * 128];  // fp16 B-frag table

// smem: points [0,147456) | feat [147456,221184) ; psum overlays [0,12288)
#define SO_FEAT 147456
#define SMEMSZ  221184

static __device__ __forceinline__ u64 pk2(float a, float b) {
    u64 r; asm("mov.b64 %0,{%1,%2};" : "=l"(r) : "f"(a), "f"(b)); return r;
}
static __device__ __forceinline__ u64 fma2(u64 a, u64 b, u64 c) {
    u64 d; asm("fma.rn.f32x2 %0,%1,%2,%3;" : "=l"(d) : "l"(a), "l"(b), "l"(c)); return d;
}
static __device__ __forceinline__ u64 add2(u64 a, u64 b) {
    u64 d; asm("add.rn.f32x2 %0,%1,%2;" : "=l"(d) : "l"(a), "l"(b)); return d;
}
static __device__ __forceinline__ void lds2(u32 a, u64& x, u64& y) {
    asm volatile("ld.shared.v2.u64 {%0,%1},[%2];" : "=l"(x), "=l"(y) : "r"(a));
}
static __device__ __forceinline__ u32 lds32(u32 a) {
    u32 v; asm volatile("ld.shared.b32 %0,[%1];" : "=r"(v) : "r"(a)); return v;
}
// f32x2 arg -> fp16x2 weight pair (lo stays lo): cvt + one ex2.approx.f16x2.
static __device__ __forceinline__ u32 wgt2(u64 t) {
    u32 h;
    asm("{\n\t.reg .f32 lo,hi;\n\tmov.b64 {lo,hi},%1;\n\t"
        "cvt.rn.f16x2.f32 %0,hi,lo;\n\tex2.approx.f16x2 %0,%0;\n\t}" : "=r"(h) : "l"(t));
    return h;
}
static __device__ __forceinline__ void mma16816(
    float& c0, float& c1, float& c2, float& c3,
    u32 a0, u32 a1, u32 a2, u32 a3, u32 b0, u32 b1) {
    asm volatile("mma.sync.aligned.m16n8k16.row.col.f32.f16.f16.f32 "
        "{%0,%1,%2,%3}, {%4,%5,%6,%7}, {%8,%9}, {%0,%1,%2,%3};"
        : "+f"(c0), "+f"(c1), "+f"(c2), "+f"(c3)
        : "r"(a0), "r"(a1), "r"(a2), "r"(a3), "r"(b0), "r"(b1));
}

__global__ void prep_kernel(const float* __restrict__ x) {
    int idx = blockIdx.x * blockDim.x + threadIdx.x;
    if (idx >= NB * NPTS) return;
    int b = idx / NPTS, n = idx - b * NPTS;
    float px = x[(b * 3 + 0) * NPTS + n];
    float py = x[(b * 3 + 1) * NPTS + n];
    float pz = x[(b * 3 + 2) * NPTS + n];
    float bn = -GG * (px * px + py * py + pz * pz);
    int jp = n >> 1, l = n & 1;
    float* base = (float*)&g_pts[b * NPTS + 2 * jp];
    base[0 + l] = px; base[2 + l] = py; base[4 + l] = pz; base[6 + l] = bn;
    g_y[0][b * NPTS + n] = make_float4(px, py, pz, 0.f);

    // fp16 B-fragment table: window = n>>4; row g: 0:x 1:y 2:z 3:1.0
    int i = n & 15;
    unsigned char* fb = g_feat + ((size_t)(b * NWINT + (n >> 4))) * 128
                      + (i >> 1) * 4 + (i & 1) * 2;
    *(__half*)(fb + 0)  = __float2half(px);
    *(__half*)(fb + 32) = __float2half(py);
    *(__half*)(fb + 64) = __float2half(pz);
    *(__half*)(fb + 96) = __float2half(1.0f);
}

__global__ __launch_bounds__(TPB, 1) void iter_kernel(int src, int dst, float* __restrict__ out) {
    extern __shared__ __align__(16) unsigned char smem[];
    const int tid = threadIdx.x, wid = tid >> 5, lane = tid & 31;
    const int g = lane >> 2, t = lane & 3;
    const int b = blockIdx.y, tile = blockIdx.x;
    u32 sb = (u32)__cvta_generic_to_shared(smem);

    {   // stage points (147456 B) + feature table (73728 B)
        const float4* gp = g_pts + b * NPTS;
        float4* sp = (float4*)smem;
        for (int i = tid; i < NPTS; i += TPB) sp[i] = gp[i];
        const float4* gf = (const float4*)(g_feat + (size_t)b * NWINT * 128);
        float4* sf = (float4*)(smem + SO_FEAT);
        for (int i = tid; i < NWINT * 8; i += TPB) sf[i] = gf[i];
    }
    __syncthreads();

    const int qp = wid & 3;            // query-pair: 32 queries
    const int js = wid >> 2;           // j-split 0..5
    const int qA0 = qp * 32 + g;
    const int qA1 = qA0 + 8;
    const int qB0 = qA0 + 16;
    const int qB1 = qA0 + 24;

    const float tg = 2.0f * GG;
    u64 axA0, ayA0, azA0, ppA0, axA1, ayA1, azA1, ppA1;
    u64 axB0, ayB0, azB0, ppB0, axB1, ayB1, azB1, ppB1;
    {
        float4 y;
        y = g_y[src][b * NPTS + tile * 128 + qA0];
        axA0 = pk2(tg * y.x, tg * y.x); ayA0 = pk2(tg * y.y, tg * y.y);
        azA0 = pk2(tg * y.z, tg * y.z);
        float p = -GG * (y.x * y.x + y.y * y.y + y.z * y.z); ppA0 = pk2(p, p);
        y = g_y[src][b * NPTS + tile * 128 + qA1];
        axA1 = pk2(tg * y.x, tg * y.x); ayA1 = pk2(tg * y.y, tg * y.y);
        azA1 = pk2(tg * y.z, tg * y.z);
        p = -GG * (y.x * y.x + y.y * y.y + y.z * y.z); ppA1 = pk2(p, p);
        y = g_y[src][b * NPTS + tile * 128 + qB0];
        axB0 = pk2(tg * y.x, tg * y.x); ayB0 = pk2(tg * y.y, tg * y.y);
        azB0 = pk2(tg * y.z, tg * y.z);
        p = -GG * (y.x * y.x + y.y * y.y + y.z * y.z); ppB0 = pk2(p, p);
        y = g_y[src][b * NPTS + tile * 128 + qB1];
        axB1 = pk2(tg * y.x, tg * y.x); ayB1 = pk2(tg * y.y, tg * y.y);
        azB1 = pk2(tg * y.z, tg * y.z);
        p = -GG * (y.x * y.x + y.y * y.y + y.z * y.z); ppB1 = pk2(p, p);
    }

    const bool ldb = (g < 4);
    const int gm = (g < 4) ? g : 3;     // clamp -> in-bounds broadcast for g>=4

    float cA0 = 0.f, cA1 = 0.f, cA2 = 0.f, cA3 = 0.f;
    float cB0 = 0.f, cB1 = 0.f, cB2 = 0.f, cB3 = 0.f;

    u32 base = sb + (u32)(js * WINS_PER_JS) * 256u + 32u * (u32)t;
    u32 fb = sb + SO_FEAT + (u32)(js * WINS_PER_JS) * 128u + (u32)(gm * 32 + t * 4);

    #pragma unroll 2
    for (int w = 0; w < WINS_PER_JS; w++, base += 256u, fb += 128u) {
        u64 xx0, yy0, zz0, bb0, xx1, yy1, zz1, bb1;
        lds2(base, xx0, yy0);
        lds2(base + 16u, zz0, bb0);
        lds2(base + 128u, xx1, yy1);
        lds2(base + 144u, zz1, bb1);

        // 8 args: 4 query rows x 2 point pairs.
        u64 tA00 = fma2(axA0, xx0, fma2(ayA0, yy0, fma2(azA0, zz0, add2(bb0, ppA0))));
        u64 tA10 = fma2(axA1, xx0, fma2(ayA1, yy0, fma2(azA1, zz0, add2(bb0, ppA1))));
        u64 tB00 = fma2(axB0, xx0, fma2(ayB0, yy0, fma2(azB0, zz0, add2(bb0, ppB0))));
        u64 tB10 = fma2(axB1, xx0, fma2(ayB1, yy0, fma2(azB1, zz0, add2(bb0, ppB1))));
        u64 tA01 = fma2(axA0, xx1, fma2(ayA0, yy1, fma2(azA0, zz1, add2(bb1, ppA0))));
        u64 tA11 = fma2(axA1, xx1, fma2(ayA1, yy1, fma2(azA1, zz1, add2(bb1, ppA1))));
        u64 tB01 = fma2(axB0, xx1, fma2(ayB0, yy1, fma2(azB0, zz1, add2(bb1, ppB0))));
        u64 tB11 = fma2(axB1, xx1, fma2(ayB1, yy1, fma2(azB1, zz1, add2(bb1, ppB1))));

        // B fragment straight from the precomputed fp16 table.
        u32 f0 = lds32(fb);
        u32 f1 = lds32(fb + 16u);
        u32 b0 = ldb ? f0 : 0u;
        u32 b1 = ldb ? f1 : 0u;

        mma16816(cA0, cA1, cA2, cA3,
                 wgt2(tA00), wgt2(tA10), wgt2(tA01), wgt2(tA11), b0, b1);
        mma16816(cB0, cB1, cB2, cB3,
                 wgt2(tB00), wgt2(tB10), wgt2(tB01), wgt2(tB11), b0, b1);
    }

    // psum overlays the points region -- everyone must be done reading points.
    __syncthreads();

    float* ps = (float*)smem;           // float4 psum[NJS][128] = 12288 B
    if (t == 0) {
        ps[(js * 128 + qA0) * 4 + 0] = cA0; ps[(js * 128 + qA0) * 4 + 1] = cA1;
        ps[(js * 128 + qA1) * 4 + 0] = cA2; ps[(js * 128 + qA1) * 4 + 1] = cA3;
        ps[(js * 128 + qB0) * 4 + 0] = cB0; ps[(js * 128 + qB0) * 4 + 1] = cB1;
        ps[(js * 128 + qB1) * 4 + 0] = cB2; ps[(js * 128 + qB1) * 4 + 1] = cB3;
    } else if (t == 1) {
        ps[(js * 128 + qA0) * 4 + 2] = cA0; ps[(js * 128 + qA0) * 4 + 3] = cA1;
        ps[(js * 128 + qA1) * 4 + 2] = cA2; ps[(js * 128 + qA1) * 4 + 3] = cA3;
        ps[(js * 128 + qB0) * 4 + 2] = cB0; ps[(js * 128 + qB0) * 4 + 3] = cB1;
        ps[(js * 128 + qB1) * 4 + 2] = cB2; ps[(js * 128 + qB1) * 4 + 3] = cB3;
    }
    __syncthreads();

    if (tid < 128) {
        float4* pv = (float4*)smem;
        float4 a = pv[tid];
        #pragma unroll
        for (int k = 1; k < NJS; k++) {
            float4 s = pv[k * 128 + tid];
            a.x += s.x; a.y += s.y; a.z += s.z; a.w += s.w;
        }
        float inv = __fdividef(1.0f, a.w);
        float nx = a.x * inv, ny = a.y * inv, nz = a.z * inv;
        int qi = tile * 128 + tid;
        g_y[dst][b * NPTS + qi] = make_float4(nx, ny, nz, 0.f);
        if (out) {
            out[(b * 3 + 0) * NPTS + qi] = nx;
            out[(b * 3 + 1) * NPTS + qi] = ny;
            out[(b * 3 + 2) * NPTS + qi] = nz;
        }
    }
}

extern "C" void kernel_launch(void* const* d_in, const int* in_sizes, int n_in,
                              void* d_out, int out_size) {
    const float* x = (const float*)d_in[0];
    float* out = (float*)d_out;

    cudaFuncSetAttribute(iter_kernel, cudaFuncAttributeMaxDynamicSharedMemorySize, SMEMSZ);

    prep_kernel<<<(NB * NPTS + 255) / 256, 256>>>(x);

    dim3 grid(72, NB);
    for (int it = 0; it < 5; it++) {
        iter_kernel<<<grid, TPB, SMEMSZ>>>(it & 1, (it & 1) ^ 1, (it == 4) ? out : nullptr);
    }
}